// round 15
// baseline (speedup 1.0000x reference)
#include <cuda_runtime.h>

#define NQ 6
#define DIM 64
#define NL 8
#define BATCH 262144
#define NCLS 4

typedef unsigned long long u64;

// Precomputed circuit operator (transposed) and folded sign/fc matrix.
// g_Wt[j*64 + i] = W[i][j]  (complex, float2 = {re, im})
__device__ float2 g_Wt[DIM * DIM];
__device__ float4 g_G[DIM];   // G[i][k] = sum_q sign(i,q) * fc_w[k][q]

__device__ __forceinline__ u64 fma2(u64 a, u64 b, u64 c) {
    u64 d;
    asm("fma.rn.f32x2 %0, %1, %2, %3;" : "=l"(d) : "l"(a), "l"(b), "l"(c));
    return d;
}

// Pack {v, v} into a 64-bit register pair (ALU pipe, not LSU).
__device__ __forceinline__ u64 dup2(float v) {
    u64 d;
    asm("mov.b64 %0, {%1, %1};" : "=l"(d) : "f"(v));
    return d;
}

__device__ __forceinline__ u64 pack2(float lo, float hi) {
    u64 d;
    asm("mov.b64 %0, {%1, %2};" : "=l"(d) : "f"(lo), "f"(hi));
    return d;
}

// {lo,hi} -> {hi,lo}
__device__ __forceinline__ u64 swap2(u64 a) {
    u64 r;
    asm("{\n\t.reg .b32 lo, hi;\n\t"
        "mov.b64 {lo, hi}, %1;\n\t"
        "mov.b64 %0, {hi, lo};\n\t}"
        : "=l"(r) : "l"(a));
    return r;
}

// ---------------------------------------------------------------------------
// Kernel 1: build the full 64x64 circuit unitary (one block, 1024 threads).
// Complex pair-updates in packed fma.rn.f32x2 form:
//   nA = u00*A + u01*B (complex) ==
//        {u00r,u00r}.A + {-u00i,u00i}.Asw + {u01r,u01r}.B + {-u01i,u01i}.Bsw
// 8 packed constants per gate precomputed once (trig out of the sweeps).
// Each layer's 6 CNOTs collapsed into ONE permutation sweep (ping-pong).
// ---------------------------------------------------------------------------
#define BW_SMEM (DIM * DIM * 8 * 2 + 48 * 8 * 8 + 64 * 4)

__global__ void build_W_kernel(const float* __restrict__ weights,
                               const float* __restrict__ fc_w) {
    extern __shared__ char bsm[];
    u64* bufA = (u64*)bsm;                       // 32 KB, state as {re,im} u64
    u64* bufB = bufA + DIM * DIM;                // 32 KB
    u64* Upk  = bufB + DIM * DIM;                // 48 gates x 8 packed consts
    int* perm = (int*)(Upk + 48 * 8);            // 64 ints

    const int tid = threadIdx.x;
    const int nthr = blockDim.x;

    // Phase 0: packed gate constants (48 threads, one trig pass)
    if (tid < NL * NQ) {
        const float phi = weights[tid * 3 + 0];
        const float th  = weights[tid * 3 + 1];
        const float om  = weights[tid * 3 + 2];
        const float ch = cosf(0.5f * th), sh = sinf(0.5f * th);
        const float a  = 0.5f * (phi + om), d = 0.5f * (phi - om);
        const float ca = cosf(a), sa = sinf(a);
        const float cd = cosf(d), sd = sinf(d);
        // u00 = ( ch*ca, -ch*sa)   u01 = (-sh*cd, -sh*sd)
        // u10 = ( sh*cd, -sh*sd)   u11 = ( ch*ca,  ch*sa)
        const float u00r =  ch * ca, u00i = -ch * sa;
        const float u01r = -sh * cd, u01i = -sh * sd;
        const float u10r =  sh * cd, u10i = -sh * sd;
        const float u11r =  ch * ca, u11i =  ch * sa;
        u64* up = Upk + tid * 8;
        up[0] = pack2(u00r, u00r);  up[1] = pack2(-u00i, u00i);
        up[2] = pack2(u01r, u01r);  up[3] = pack2(-u01i, u01i);
        up[4] = pack2(u10r, u10r);  up[5] = pack2(-u10i, u10i);
        up[6] = pack2(u11r, u11r);  up[7] = pack2(-u11i, u11i);
    }

    // Init A = I  ({1.0f, 0.0f} on diagonal)
    for (int idx = tid; idx < DIM * DIM; idx += nthr) {
        int i = idx >> 6, j = idx & 63;
        bufA[idx] = (i == j) ? 0x000000003F800000ULL : 0ULL;
    }
    __syncthreads();

    u64* cur = bufA;
    u64* nxt = bufB;

    for (int l = 0; l < NL; l++) {
        // --- rotation sweeps (in place on cur), packed complex math ---
        for (int q = 0; q < NQ; q++) {
            const int b = 5 - q;
            const int mask = 1 << b;
            const u64* up = Upk + (l * NQ + q) * 8;
            const u64 c00r = up[0], c00i = up[1];
            const u64 c01r = up[2], c01i = up[3];
            const u64 c10r = up[4], c10i = up[5];
            const u64 c11r = up[6], c11i = up[7];

            for (int idx = tid; idx < 32 * DIM; idx += nthr) {
                const int j  = idx & 63;
                const int pr = idx >> 6;                       // 5-bit
                const int r0 = ((pr >> b) << (b + 1)) | (pr & (mask - 1));
                const int r1 = r0 | mask;
                const u64 pA  = cur[r0 * 64 + j];
                const u64 pB  = cur[r1 * 64 + j];
                const u64 pAs = swap2(pA);
                const u64 pBs = swap2(pB);
                u64 nA = fma2(c01i, pBs, 0ULL);
                nA = fma2(c01r, pB, nA);
                nA = fma2(c00i, pAs, nA);
                nA = fma2(c00r, pA, nA);
                u64 nB = fma2(c11i, pBs, 0ULL);
                nB = fma2(c11r, pB, nB);
                nB = fma2(c10i, pAs, nB);
                nB = fma2(c10r, pA, nB);
                cur[r0 * 64 + j] = nA;
                cur[r1 * 64 + j] = nB;
            }
            __syncthreads();
        }

        // --- full CNOT-ring permutation: one ping-pong scatter sweep ---
        const int r = (l % (NQ - 1)) + 1;
        if (tid < DIM) {
            int y = tid;
            for (int q = 0; q < NQ; q++) {
                const int bc = 5 - q;
                const int bt = 5 - ((q + r) % NQ);
                y ^= ((y >> bc) & 1) << bt;
            }
            perm[tid] = y;     // B[sigma(x)] = A[x]
        }
        __syncthreads();
        for (int idx = tid; idx < DIM * DIM; idx += nthr) {
            const int x = idx >> 6, j = idx & 63;
            nxt[perm[x] * 64 + j] = cur[idx];
        }
        __syncthreads();
        u64* t = cur; cur = nxt; nxt = t;
    }

    // Write transposed operator: g_Wt[j*64+i] = M[i][j]
    u64* Wt = (u64*)g_Wt;
    for (int idx = tid; idx < DIM * DIM; idx += nthr) {
        const int j = idx >> 6, i = idx & 63;
        Wt[idx] = cur[i * 64 + j];
    }
    // Folded sign/fc matrix G
    for (int i = tid; i < DIM; i += nthr) {
        float4 g = make_float4(0.f, 0.f, 0.f, 0.f);
        for (int q = 0; q < NQ; q++) {
            const float sgn = ((i >> (5 - q)) & 1) ? -1.0f : 1.0f;
            g.x += sgn * fc_w[0 * NQ + q];
            g.y += sgn * fc_w[1 * NQ + q];
            g.z += sgn * fc_w[2 * NQ + q];
            g.w += sgn * fc_w[3 * NQ + q];
        }
        g_G[i] = g;
    }
}

// ---------------------------------------------------------------------------
// Kernel 2: batched complex matvec via packed fma.rn.f32x2.
// One warp handles 8 samples per chunk; lane t owns output rows 2t, 2t+1.
// 3 blocks/SM (85-reg cap): n2 lives in warp scratch, G/bias loaded only in
// the epilogue, to keep the persistent register set small.
// ---------------------------------------------------------------------------
#define BLK 256
#define WPB (BLK / 32)
#define SPW 8
#define STAGE_STRIDE 272                        // bytes/sample: 64 floats + pad
#define EPI_STRIDE 528                          // bytes/sample for epilogue
#define N2_OFF 4224                             // n2[8] floats after epi region
#define WARP_SCRATCH 4352                       // 128B aligned
#define SMEM_BYTES (DIM * DIM * 8 + WPB * WARP_SCRATCH)   // 32768 + 34816

__global__ __launch_bounds__(BLK, 3) void qnn_main_kernel(
    const float* __restrict__ x,
    const float* __restrict__ fc_b,
    float* __restrict__ out) {
    extern __shared__ char smem[];
    // W region: [j][lane] as ulonglong2 = {{re0,im0},{re1,im1}} rows 2lane,2lane+1
    ulonglong2* WshQ = (ulonglong2*)smem;
    char* scratch_all = smem + DIM * DIM * 8;

    const int tid  = threadIdx.x;
    const int warp = tid >> 5;
    const int lane = tid & 31;

    {
        const ulonglong2* Wg = (const ulonglong2*)g_Wt;
#pragma unroll
        for (int idx = tid; idx < DIM * DIM / 2; idx += BLK) WshQ[idx] = Wg[idx];
    }
    __syncthreads();

    char* scr = scratch_all + warp * WARP_SCRATCH;

    const int gwarp   = blockIdx.x * WPB + warp;
    const int nwarps  = gridDim.x * WPB;
    const int nchunks = BATCH / SPW;

    for (int chunk = gwarp; chunk < nchunks; chunk += nwarps) {
        const int b0 = chunk * SPW;

        // ---- load 8 samples, squared norms -> scratch, stage plain ----
        __syncwarp();
#pragma unroll
        for (int s = 0; s < SPW; s++) {
            float2 v = ((const float2*)(x + (size_t)(b0 + s) * DIM))[lane];
            float sq = fmaf(v.x, v.x, v.y * v.y);
#pragma unroll
            for (int off = 16; off > 0; off >>= 1)
                sq += __shfl_xor_sync(0xffffffffu, sq, off);
            if (lane == 0) ((float*)(scr + N2_OFF))[s] = sq;
            ((float2*)(scr + s * STAGE_STRIDE))[lane] = v;
        }
        __syncwarp();

        // ---- y = W x for 8 samples; packed complex accumulators ----
        u64 acc0[SPW], acc1[SPW];
#pragma unroll
        for (int s = 0; s < SPW; s++) { acc0[s] = 0ull; acc1[s] = 0ull; }

#pragma unroll 2
        for (int j4 = 0; j4 < DIM / 4; j4++) {
            const ulonglong2 wq0 = WshQ[(j4 * 4 + 0) * 32 + lane];
            const ulonglong2 wq1 = WshQ[(j4 * 4 + 1) * 32 + lane];
            const ulonglong2 wq2 = WshQ[(j4 * 4 + 2) * 32 + lane];
            const ulonglong2 wq3 = WshQ[(j4 * 4 + 3) * 32 + lane];
#pragma unroll
            for (int s = 0; s < SPW; s++) {
                const float4 xv =
                    *(const float4*)(scr + s * STAGE_STRIDE + j4 * 16);
                const u64 x0 = dup2(xv.x);
                const u64 x1 = dup2(xv.y);
                const u64 x2 = dup2(xv.z);
                const u64 x3 = dup2(xv.w);
                acc0[s] = fma2(wq0.x, x0, acc0[s]);
                acc1[s] = fma2(wq0.y, x0, acc1[s]);
                acc0[s] = fma2(wq1.x, x1, acc0[s]);
                acc1[s] = fma2(wq1.y, x1, acc1[s]);
                acc0[s] = fma2(wq2.x, x2, acc0[s]);
                acc1[s] = fma2(wq2.y, x2, acc1[s]);
                acc0[s] = fma2(wq3.x, x3, acc0[s]);
                acc1[s] = fma2(wq3.y, x3, acc1[s]);
            }
        }

        // ---- epilogue: probs -> folded head -> shared transpose reduce ----
        __syncwarp();
        {
            const float4 Ga = g_G[2 * lane];
            const float4 Gb = g_G[2 * lane + 1];
#pragma unroll
            for (int s = 0; s < SPW; s++) {
                const float n2s = ((const float*)(scr + N2_OFF))[s];
                const float inv = 1.0f / fmaxf(n2s, 1e-24f);
                float r0, i0, r1, i1;
                asm("mov.b64 {%0, %1}, %2;" : "=f"(r0), "=f"(i0) : "l"(acc0[s]));
                asm("mov.b64 {%0, %1}, %2;" : "=f"(r1), "=f"(i1) : "l"(acc1[s]));
                const float p0 = fmaf(r0, r0, i0 * i0) * inv;
                const float p1 = fmaf(r1, r1, i1 * i1) * inv;
                float4 part;
                part.x = fmaf(p0, Ga.x, p1 * Gb.x);
                part.y = fmaf(p0, Ga.y, p1 * Gb.y);
                part.z = fmaf(p0, Ga.z, p1 * Gb.z);
                part.w = fmaf(p0, Ga.w, p1 * Gb.w);
                ((float4*)(scr + s * EPI_STRIDE))[lane] = part;
            }
        }
        __syncwarp();

        // lane -> (sample = lane>>2, class = lane&3); sum 32 partials.
        {
            const int s = lane >> 2;
            const int c = lane & 3;
            const float* base = (const float*)(scr + s * EPI_STRIDE) + c;
            float a0 = 0.f, a1 = 0.f, a2 = 0.f, a3 = 0.f;
#pragma unroll
            for (int l = 0; l < 32; l += 4) {
                a0 += base[(l + 0) * 4];
                a1 += base[(l + 1) * 4];
                a2 += base[(l + 2) * 4];
                a3 += base[(l + 3) * 4];
            }
            const float res = (a0 + a1) + (a2 + a3) + fc_b[c];
            out[(size_t)b0 * NCLS + lane] = res;   // fully coalesced 128B
        }
        __syncwarp();
    }
}

// ---------------------------------------------------------------------------
// Launch
// ---------------------------------------------------------------------------
extern "C" void kernel_launch(void* const* d_in, const int* in_sizes, int n_in,
                              void* d_out, int out_size) {
    const float* x       = (const float*)d_in[0];   // [262144, 64]
    const float* weights = (const float*)d_in[1];   // [8, 6, 3]
    const float* fc_w    = (const float*)d_in[2];   // [4, 6]
    const float* fc_b    = (const float*)d_in[3];   // [4]
    float* out           = (float*)d_out;           // [262144, 4]

    (void)in_sizes; (void)n_in; (void)out_size;

    static int attr_done = 0;
    if (!attr_done) {
        cudaFuncSetAttribute(qnn_main_kernel,
                             cudaFuncAttributeMaxDynamicSharedMemorySize,
                             SMEM_BYTES);
        cudaFuncSetAttribute(build_W_kernel,
                             cudaFuncAttributeMaxDynamicSharedMemorySize,
                             BW_SMEM);
        attr_done = 1;
    }

    build_W_kernel<<<1, 1024, BW_SMEM>>>(weights, fc_w);
    qnn_main_kernel<<<456, BLK, SMEM_BYTES>>>(x, fc_b, out);
}